// round 2
// baseline (speedup 1.0000x reference)
#include <cuda_runtime.h>
#include <cstdint>

#define NPTS 8192
#define NB   4
#define NC   64
#define NK   16
#define BNSCALE 0.9999950000374997f

// ---------------- device scratch (no allocation allowed) ----------------
__device__ __align__(16) float dZ[NB * NPTS * NC];   // z[b][n][c], 64 floats/row contiguous
__device__ float dX1[NB * NC * NPTS];                // x after block 0
// fused parameters per layer
__device__ float dW1f[2][NC * 3];
__device__ float dC0 [2][NC];
__device__ __align__(16) float dM  [2][NC * NC];
__device__ float dC1 [2][NC];
__device__ float dA1T[2][NC * NC];                   // A1f transposed: [m][c]
__device__ __align__(16) float dA2 [2][NC * NC];
__device__ float dC2 [2][NC];
__device__ __align__(16) float dD  [2][NC * NC];
__device__ float dCd [2][NC];

// ---------------- prep: fold BN affines, fuse aw1*S2*dw2 into M ---------
__global__ void prep_kernel(
    const float* __restrict__ dw1, const float* __restrict__ db1,
    const float* __restrict__ dg1, const float* __restrict__ dbe1,
    const float* __restrict__ dw2, const float* __restrict__ db2,
    const float* __restrict__ dg2, const float* __restrict__ dbe2,
    const float* __restrict__ aw1, const float* __restrict__ ab1,
    const float* __restrict__ ag1, const float* __restrict__ abe1,
    const float* __restrict__ aw2, const float* __restrict__ ab2,
    const float* __restrict__ ag2, const float* __restrict__ abe2,
    const float* __restrict__ lw,  const float* __restrict__ lb,
    const float* __restrict__ lg,  const float* __restrict__ lbe)
{
    int L = blockIdx.x;
    int o = threadIdx.x;
    int vo = L * NC + o;
    float S1  = dg1[vo] * BNSCALE;
    float Sa1 = ag1[vo] * BNSCALE;
    float Sa2 = ag2[vo] * BNSCALE;
    float Sd  = lg [vo] * BNSCALE;

    #pragma unroll
    for (int j = 0; j < 3; j++) dW1f[L][o * 3 + j] = S1 * dw1[vo * 3 + j];
    dC0[L][o] = fmaf(S1, db1[vo], dbe1[vo]);

    float Mrow[NC];
    #pragma unroll
    for (int c = 0; c < NC; c++) Mrow[c] = 0.f;
    float t2dot = 0.f;
    for (int m = 0; m < NC; m++) {
        int vm = L * NC + m;
        float S2m = dg2[vm] * BNSCALE;
        float w   = aw1[vo * NC + m];
        t2dot = fmaf(w, fmaf(S2m, db2[vm], dbe2[vm]), t2dot);
        float ws = w * S2m;
        #pragma unroll
        for (int c = 0; c < NC; c++) Mrow[c] = fmaf(ws, dw2[vm * NC + c], Mrow[c]);
        dA1T[L][m * NC + o] = Sa1 * w;   // A1f[o][m] stored transposed
    }
    #pragma unroll
    for (int c = 0; c < NC; c++) dM[L][o * NC + c] = Sa1 * Mrow[c];
    dC1[L][o] = fmaf(Sa1, t2dot + ab1[vo], abe1[vo]);

    #pragma unroll
    for (int c = 0; c < NC; c++) dA2[L][o * NC + c] = Sa2 * aw2[vo * NC + c];
    dC2[L][o] = fmaf(Sa2, ab2[vo], abe2[vo]);
    #pragma unroll
    for (int c = 0; c < NC; c++) dD[L][o * NC + c] = Sd * lw[vo * NC + c];
    dCd[L][o] = fmaf(Sd, lb[vo], lbe[vo]);
}

// ---------------- z = A1f @ x  (per batch, 64xN) ------------------------
__global__ void z_kernel(const float* __restrict__ x_param, int layer)
{
    __shared__ float As[NC * NC];      // A1T: [m][c]
    __shared__ float xs[NC * NC];      // [m][nl]
    const float* x = layer ? dX1 : x_param;
    int tid = threadIdx.x;
    int b = blockIdx.y;
    int n0 = blockIdx.x * 64;

    for (int i = tid; i < NC * NC; i += 256) As[i] = dA1T[layer][i];
    for (int i = tid; i < NC * NC; i += 256) {
        int m = i >> 6, nl = i & 63;
        xs[i] = x[((size_t)(b * NC + m)) * NPTS + n0 + nl];
    }
    __syncthreads();

    int c  = tid & 63;
    int nb = tid >> 6;   // 0..3
    for (int nl = nb; nl < 64; nl += 4) {
        float acc = 0.f;
        #pragma unroll
        for (int m = 0; m < NC; m++) acc = fmaf(As[m * 64 + c], xs[m * 64 + nl], acc);
        dZ[(((size_t)b * NPTS) + n0 + nl) * 64 + c] = acc;
    }
}

// ---------------- main fused kernel: 2 threads per point ----------------
#define DOT4A(acc, mm, v0, v1, v2, v3) \
    acc = fmaf((mm).x, (v0), fmaf((mm).y, (v1), fmaf((mm).z, (v2), fmaf((mm).w, (v3), (acc)))))

__global__ void main_kernel(
    const float* __restrict__ p, const float* __restrict__ x_param,
    const int* __restrict__ idx, float* __restrict__ out_param, int layer)
{
    __shared__ float Ms [NC * NC];
    __shared__ float A2s[NC * NC];
    __shared__ float W1s[NC * 3];
    __shared__ float c0s[NC], c1s[NC], c2s[NC], cds[NC];

    int tid = threadIdx.x;
    for (int i = tid; i < NC * NC; i += 128) { Ms[i] = dM[layer][i]; A2s[i] = dA2[layer][i]; }
    for (int i = tid; i < NC * 3; i += 128) W1s[i] = dW1f[layer][i];
    if (tid < NC) {
        c0s[tid] = dC0[layer][tid]; c1s[tid] = dC1[layer][tid];
        c2s[tid] = dC2[layer][tid]; cds[tid] = dCd[layer][tid];
    }
    __syncthreads();

    int hf = tid & 1;                 // which half of the 64 channels this thread owns
    int rb = hf * 32;                 // row/col base of own half
    int g  = blockIdx.x * 64 + (tid >> 1);
    int b  = g >> 13;
    int n  = g & (NPTS - 1);

    const float* pb = p + (size_t)b * 3 * NPTS;
    float pnx = pb[n], pny = pb[NPTS + n], pnz = pb[2 * NPTS + n];
    const int* ip = idx + ((size_t)(b * NPTS) + n) * NK;
    const float* zb = dZ + (size_t)b * NPTS * NC;

    const float* x_in  = layer ? dX1 : x_param;
    float*       x_out = layer ? out_param : dX1;

    const float4* Ms4  = (const float4*)Ms;
    const float4* A2s4 = (const float4*)A2s;

    float y[32];
    #pragma unroll
    for (int i = 0; i < 32; i++) y[i] = 0.f;   // a = relu(..) >= 0, so 0 is a safe identity

    #pragma unroll 1
    for (int k = 0; k < NK; k++) {
        int j = ip[k];
        float rx = pnx - pb[j];
        float ry = pny - pb[NPTS + j];
        float rz = pnz - pb[2 * NPTS + j];

        // h = relu(W1f @ rel + c0)   (full 64, duplicated across the pair)
        float h[NC];
        #pragma unroll
        for (int o = 0; o < NC; o++)
            h[o] = fmaxf(fmaf(W1s[o * 3], rx,
                        fmaf(W1s[o * 3 + 1], ry,
                        fmaf(W1s[o * 3 + 2], rz, c0s[o]))), 0.f);

        // v[own half] = relu(M[own rows] @ h + z_j[own half] + c1)
        float v[32];
        const float4* zr = (const float4*)(zb + (size_t)j * NC) + hf * 8;
        #pragma unroll
        for (int og = 0; og < 8; og++) {
            float4 z4 = zr[og];
            int r0 = rb + og * 4;
            float a0 = z4.x + c1s[r0 + 0];
            float a1 = z4.y + c1s[r0 + 1];
            float a2 = z4.z + c1s[r0 + 2];
            float a3 = z4.w + c1s[r0 + 3];
            #pragma unroll
            for (int cg = 0; cg < 16; cg++) {
                float h0 = h[cg * 4], h1 = h[cg * 4 + 1], h2 = h[cg * 4 + 2], h3 = h[cg * 4 + 3];
                float4 m0 = Ms4[(r0 + 0) * 16 + cg];
                float4 m1 = Ms4[(r0 + 1) * 16 + cg];
                float4 m2 = Ms4[(r0 + 2) * 16 + cg];
                float4 m3 = Ms4[(r0 + 3) * 16 + cg];
                DOT4A(a0, m0, h0, h1, h2, h3);
                DOT4A(a1, m1, h0, h1, h2, h3);
                DOT4A(a2, m2, h0, h1, h2, h3);
                DOT4A(a3, m3, h0, h1, h2, h3);
            }
            v[og * 4 + 0] = fmaxf(a0, 0.f);
            v[og * 4 + 1] = fmaxf(a1, 0.f);
            v[og * 4 + 2] = fmaxf(a2, 0.f);
            v[og * 4 + 3] = fmaxf(a3, 0.f);
        }

        // a = relu(A2 @ v + c2); y = max(y, a)
        // own-col partials for own rows (a*) and partner rows (b*), combine via shfl.
        #pragma unroll
        for (int og = 0; og < 8; og++) {
            int r0 = rb + og * 4;            // own rows
            int q0 = (rb ^ 32) + og * 4;     // partner rows
            float a0 = 0.f, a1 = 0.f, a2 = 0.f, a3 = 0.f;
            float b0 = 0.f, b1 = 0.f, b2 = 0.f, b3 = 0.f;
            #pragma unroll
            for (int cg = 0; cg < 8; cg++) {
                float v0 = v[cg * 4], v1 = v[cg * 4 + 1], v2 = v[cg * 4 + 2], v3 = v[cg * 4 + 3];
                int co = hf * 8 + cg;        // own column group
                float4 m;
                m = A2s4[(r0 + 0) * 16 + co]; DOT4A(a0, m, v0, v1, v2, v3);
                m = A2s4[(r0 + 1) * 16 + co]; DOT4A(a1, m, v0, v1, v2, v3);
                m = A2s4[(r0 + 2) * 16 + co]; DOT4A(a2, m, v0, v1, v2, v3);
                m = A2s4[(r0 + 3) * 16 + co]; DOT4A(a3, m, v0, v1, v2, v3);
                m = A2s4[(q0 + 0) * 16 + co]; DOT4A(b0, m, v0, v1, v2, v3);
                m = A2s4[(q0 + 1) * 16 + co]; DOT4A(b1, m, v0, v1, v2, v3);
                m = A2s4[(q0 + 2) * 16 + co]; DOT4A(b2, m, v0, v1, v2, v3);
                m = A2s4[(q0 + 3) * 16 + co]; DOT4A(b3, m, v0, v1, v2, v3);
            }
            float s0 = __shfl_xor_sync(0xffffffffu, b0, 1);
            float s1 = __shfl_xor_sync(0xffffffffu, b1, 1);
            float s2 = __shfl_xor_sync(0xffffffffu, b2, 1);
            float s3 = __shfl_xor_sync(0xffffffffu, b3, 1);
            y[og * 4 + 0] = fmaxf(y[og * 4 + 0], fmaxf(a0 + s0 + c2s[r0 + 0], 0.f));
            y[og * 4 + 1] = fmaxf(y[og * 4 + 1], fmaxf(a1 + s1 + c2s[r0 + 1], 0.f));
            y[og * 4 + 2] = fmaxf(y[og * 4 + 2], fmaxf(a2 + s2 + c2s[r0 + 2], 0.f));
            y[og * 4 + 3] = fmaxf(y[og * 4 + 3], fmaxf(a3 + s3 + c2s[r0 + 3], 0.f));
        }
    }

    // out = D @ y + cd + x_in   (same pair-split + shfl combine; D via __ldg)
    const float4* D4 = (const float4*)dD[layer];
    float*       xo = x_out + ((size_t)b * NC) * NPTS + n;
    const float* xi = x_in  + ((size_t)b * NC) * NPTS + n;
    #pragma unroll
    for (int og = 0; og < 8; og++) {
        int r0 = rb + og * 4;
        int q0 = (rb ^ 32) + og * 4;
        float a0 = 0.f, a1 = 0.f, a2 = 0.f, a3 = 0.f;
        float b0 = 0.f, b1 = 0.f, b2 = 0.f, b3 = 0.f;
        #pragma unroll
        for (int cg = 0; cg < 8; cg++) {
            float y0 = y[cg * 4], y1 = y[cg * 4 + 1], y2 = y[cg * 4 + 2], y3 = y[cg * 4 + 3];
            int co = hf * 8 + cg;
            float4 m;
            m = __ldg(&D4[(r0 + 0) * 16 + co]); DOT4A(a0, m, y0, y1, y2, y3);
            m = __ldg(&D4[(r0 + 1) * 16 + co]); DOT4A(a1, m, y0, y1, y2, y3);
            m = __ldg(&D4[(r0 + 2) * 16 + co]); DOT4A(a2, m, y0, y1, y2, y3);
            m = __ldg(&D4[(r0 + 3) * 16 + co]); DOT4A(a3, m, y0, y1, y2, y3);
            m = __ldg(&D4[(q0 + 0) * 16 + co]); DOT4A(b0, m, y0, y1, y2, y3);
            m = __ldg(&D4[(q0 + 1) * 16 + co]); DOT4A(b1, m, y0, y1, y2, y3);
            m = __ldg(&D4[(q0 + 2) * 16 + co]); DOT4A(b2, m, y0, y1, y2, y3);
            m = __ldg(&D4[(q0 + 3) * 16 + co]); DOT4A(b3, m, y0, y1, y2, y3);
        }
        float s0 = __shfl_xor_sync(0xffffffffu, b0, 1);
        float s1 = __shfl_xor_sync(0xffffffffu, b1, 1);
        float s2 = __shfl_xor_sync(0xffffffffu, b2, 1);
        float s3 = __shfl_xor_sync(0xffffffffu, b3, 1);
        xo[(r0 + 0) * NPTS] = a0 + s0 + cds[r0 + 0] + xi[(r0 + 0) * NPTS];
        xo[(r0 + 1) * NPTS] = a1 + s1 + cds[r0 + 1] + xi[(r0 + 1) * NPTS];
        xo[(r0 + 2) * NPTS] = a2 + s2 + cds[r0 + 2] + xi[(r0 + 2) * NPTS];
        xo[(r0 + 3) * NPTS] = a3 + s3 + cds[r0 + 3] + xi[(r0 + 3) * NPTS];
    }
}

// ---------------- launch ------------------------------------------------
extern "C" void kernel_launch(void* const* d_in, const int* in_sizes, int n_in,
                              void* d_out, int out_size)
{
    const float* p   = (const float*)d_in[0];   // (B,3,N)
    const float* x   = (const float*)d_in[1];   // (B,C,N)
    const int*   idx = (const int*)d_in[2];     // (B,N,K)

    prep_kernel<<<2, 64>>>(
        (const float*)d_in[3],  (const float*)d_in[4],  (const float*)d_in[5],  (const float*)d_in[6],
        (const float*)d_in[7],  (const float*)d_in[8],  (const float*)d_in[9],  (const float*)d_in[10],
        (const float*)d_in[11], (const float*)d_in[12], (const float*)d_in[13], (const float*)d_in[14],
        (const float*)d_in[15], (const float*)d_in[16], (const float*)d_in[17], (const float*)d_in[18],
        (const float*)d_in[19], (const float*)d_in[20], (const float*)d_in[21], (const float*)d_in[22]);

    float* out_p = (float*)d_out;                       // (B,3,N) passthrough
    float* out_x = (float*)d_out + NB * 3 * NPTS;       // (B,C,N)

    cudaMemcpyAsync(out_p, p, (size_t)NB * 3 * NPTS * sizeof(float),
                    cudaMemcpyDeviceToDevice);

    dim3 zgrid(NPTS / 64, NB);
    // layer 0: x -> dX1
    z_kernel<<<zgrid, 256>>>(x, 0);
    main_kernel<<<(NB * NPTS + 63) / 64, 128>>>(p, x, idx, out_x, 0);
    // layer 1: dX1 -> out_x
    z_kernel<<<zgrid, 256>>>(x, 1);
    main_kernel<<<(NB * NPTS + 63) / 64, 128>>>(p, x, idx, out_x, 1);
}